// round 3
// baseline (speedup 1.0000x reference)
#include <cuda_runtime.h>
#include <math.h>

#define B_    2
#define S_    2048
#define H_    2048
#define NH_   32
#define NKV_  8
#define D_    64
#define GROUPS_ (NH_/NKV_)
#define SCALE_ 0.125f   // D^-0.5 = 1/8

// ---------------- scratch (device globals; no allocs allowed) ----------------
__device__ float g_q[(size_t)B_*S_*NH_*D_];   // [b*S+s][h*64+d]  33.5 MB
__device__ float g_k[(size_t)B_*S_*NKV_*D_];  //  8.4 MB
__device__ float g_v[(size_t)B_*S_*NKV_*D_];  //  8.4 MB
__device__ float g_o[(size_t)B_*S_*NH_*D_];   // attn out, 33.5 MB

// ---------------- SGEMM: C[M,N] = A[M,K] * W[N,K]^T (all row-major) ----------
// 128x128x16 tiles, 256 threads, 8x8 microtile, transposed smem staging.
__global__ void __launch_bounds__(256) sgemm_tn(
    const float* __restrict__ A, const float* __restrict__ W,
    float* __restrict__ C, int M, int N, int K)
{
    __shared__ float As[16][132];
    __shared__ float Bs[16][132];

    const int tid = threadIdx.x;
    const int tx = tid & 15;        // n dir
    const int ty = tid >> 4;        // m dir
    const int bm = blockIdx.y * 128;
    const int bn = blockIdx.x * 128;

    const float* Ag = A + (size_t)bm * K;
    const float* Bg = W + (size_t)bn * K;

    float acc[8][8];
#pragma unroll
    for (int i = 0; i < 8; ++i)
#pragma unroll
        for (int j = 0; j < 8; ++j) acc[i][j] = 0.f;

    const int lr = tid >> 2;          // 0..63
    const int lc = (tid & 3) << 2;    // 0,4,8,12

    for (int k0 = 0; k0 < K; k0 += 16) {
#pragma unroll
        for (int hrow = 0; hrow < 2; ++hrow) {
            int row = lr + hrow * 64;
            float4 av = *(const float4*)(Ag + (size_t)row * K + k0 + lc);
            As[lc+0][row] = av.x; As[lc+1][row] = av.y;
            As[lc+2][row] = av.z; As[lc+3][row] = av.w;
            float4 bv = *(const float4*)(Bg + (size_t)row * K + k0 + lc);
            Bs[lc+0][row] = bv.x; Bs[lc+1][row] = bv.y;
            Bs[lc+2][row] = bv.z; Bs[lc+3][row] = bv.w;
        }
        __syncthreads();

#pragma unroll
        for (int kk = 0; kk < 16; ++kk) {
            float4 a0 = *(const float4*)&As[kk][ty*8];
            float4 a1 = *(const float4*)&As[kk][ty*8+4];
            float4 b0 = *(const float4*)&Bs[kk][tx*8];
            float4 b1 = *(const float4*)&Bs[kk][tx*8+4];
            float a[8] = {a0.x,a0.y,a0.z,a0.w,a1.x,a1.y,a1.z,a1.w};
            float b[8] = {b0.x,b0.y,b0.z,b0.w,b1.x,b1.y,b1.z,b1.w};
#pragma unroll
            for (int i = 0; i < 8; ++i)
#pragma unroll
                for (int j = 0; j < 8; ++j)
                    acc[i][j] = fmaf(a[i], b[j], acc[i][j]);
        }
        __syncthreads();
    }

    float* Cg = C + (size_t)(bm + ty*8) * N + bn + tx*8;
#pragma unroll
    for (int i = 0; i < 8; ++i) {
        *(float4*)(Cg + (size_t)i*N)     = make_float4(acc[i][0],acc[i][1],acc[i][2],acc[i][3]);
        *(float4*)(Cg + (size_t)i*N + 4) = make_float4(acc[i][4],acc[i][5],acc[i][6],acc[i][7]);
    }
}

// ---------------- RoPE (in-place, paired halves) ----------------------------
__global__ void rope_kernel(float* __restrict__ buf,
                            const float* __restrict__ cosb,
                            const float* __restrict__ sinb,
                            int nheads)
{
    int idx = blockIdx.x * blockDim.x + threadIdx.x;
    int total = B_ * S_ * nheads * (D_/2);
    if (idx >= total) return;
    int d   = idx % (D_/2);
    int h   = (idx / (D_/2)) % nheads;
    int row = idx / ((D_/2) * nheads);         // b*S + s
    size_t base = (size_t)row * nheads * D_ + (size_t)h * D_;
    float q1 = buf[base + d];
    float q2 = buf[base + d + D_/2];
    float c1 = cosb[(size_t)row * D_ + d];
    float c2 = cosb[(size_t)row * D_ + d + D_/2];
    float s1 = sinb[(size_t)row * D_ + d];
    float s2 = sinb[(size_t)row * D_ + d + D_/2];
    buf[base + d]        = q1 * c1 - q2 * s1;   // first half: q*cos - x2*sin
    buf[base + d + D_/2] = q2 * c2 + q1 * s2;   // second half: q*cos + x1*sin
}

// ---------------- Fused causal flash attention (GQA) -------------------------
// BM=BN=64, D=64, 256 threads (16x16 grid), 4x4 microtiles, online softmax.
__global__ void __launch_bounds__(256) flash_kernel(
    const float* __restrict__ Q, const float* __restrict__ K,
    const float* __restrict__ V, float* __restrict__ O)
{
    __shared__ float Qs[64*64];   // transposed: [d][qrow]
    __shared__ float KVs[64*64];  // K phase: [d][key] ; V phase: [key][d]
    __shared__ float Ps[64*64];   // [qrow][key]

    const int tid = threadIdx.x;
    const int tx = tid & 15;              // key-col / d-col group
    const int ty = tid >> 4;              // q-row group
    const int bh = blockIdx.y;
    const int b  = bh / NH_;
    const int h  = bh % NH_;
    const int kvh = h / GROUPS_;
    const int qt = blockIdx.x;
    const int q0 = qt * 64;

    const float* Qbase = Q + (size_t)b * S_ * NH_  * D_ + (size_t)h   * D_;
    const float* Kbase = K + (size_t)b * S_ * NKV_ * D_ + (size_t)kvh * D_;
    const float* Vbase = V + (size_t)b * S_ * NKV_ * D_ + (size_t)kvh * D_;

    // load Q tile transposed
    {
        int r  = tid >> 2;            // 0..63
        int c0 = (tid & 3) * 16;
        const float* src = Qbase + (size_t)(q0 + r) * NH_ * D_;
#pragma unroll
        for (int c = 0; c < 16; c += 4) {
            float4 v = *(const float4*)(src + c0 + c);
            Qs[(c0+c+0)*64 + r] = v.x;
            Qs[(c0+c+1)*64 + r] = v.y;
            Qs[(c0+c+2)*64 + r] = v.z;
            Qs[(c0+c+3)*64 + r] = v.w;
        }
    }

    float m_i[4], l_i[4], acc[4][4];
#pragma unroll
    for (int i = 0; i < 4; ++i) {
        m_i[i] = -1e30f; l_i[i] = 0.f;
#pragma unroll
        for (int j = 0; j < 4; ++j) acc[i][j] = 0.f;
    }

    const int ntiles = qt + 1;
    for (int t = 0; t < ntiles; ++t) {
        const int k0 = t * 64;
        __syncthreads();  // KVs/Ps safe to overwrite (also covers Q load on t=0)

        // load K tile transposed: KVs[d][key]
        {
            int r  = tid >> 2;
            int c0 = (tid & 3) * 16;
            const float* src = Kbase + (size_t)(k0 + r) * NKV_ * D_;
#pragma unroll
            for (int c = 0; c < 16; c += 4) {
                float4 v = *(const float4*)(src + c0 + c);
                KVs[(c0+c+0)*64 + r] = v.x;
                KVs[(c0+c+1)*64 + r] = v.y;
                KVs[(c0+c+2)*64 + r] = v.z;
                KVs[(c0+c+3)*64 + r] = v.w;
            }
        }
        __syncthreads();

        // S = Q K^T  (64x64x64)
        float s[4][4];
#pragma unroll
        for (int i = 0; i < 4; ++i)
#pragma unroll
            for (int j = 0; j < 4; ++j) s[i][j] = 0.f;

#pragma unroll 4
        for (int kk = 0; kk < 64; ++kk) {
            float4 qa = *(const float4*)&Qs[kk*64 + ty*4];
            float4 kb = *(const float4*)&KVs[kk*64 + tx*4];
            float a[4] = {qa.x, qa.y, qa.z, qa.w};
            float c[4] = {kb.x, kb.y, kb.z, kb.w};
#pragma unroll
            for (int i = 0; i < 4; ++i)
#pragma unroll
                for (int j = 0; j < 4; ++j)
                    s[i][j] = fmaf(a[i], c[j], s[i][j]);
        }

        // online softmax per q-row (reduce across the 16 tx threads)
#pragma unroll
        for (int i = 0; i < 4; ++i) {
            int qrow = q0 + ty*4 + i;
            float mloc = -1e30f;
#pragma unroll
            for (int j = 0; j < 4; ++j) {
                int kcol = k0 + tx*4 + j;
                float val = s[i][j] * SCALE_;
                if (kcol > qrow) val = -1e30f;
                s[i][j] = val;
                mloc = fmaxf(mloc, val);
            }
#pragma unroll
            for (int off = 8; off > 0; off >>= 1)
                mloc = fmaxf(mloc, __shfl_xor_sync(0xffffffffu, mloc, off, 16));
            float mnew = fmaxf(m_i[i], mloc);
            float alpha = __expf(m_i[i] - mnew);
            float rsum = 0.f;
#pragma unroll
            for (int j = 0; j < 4; ++j) {
                s[i][j] = __expf(s[i][j] - mnew);
                rsum += s[i][j];
            }
#pragma unroll
            for (int off = 8; off > 0; off >>= 1)
                rsum += __shfl_xor_sync(0xffffffffu, rsum, off, 16);
            l_i[i] = l_i[i] * alpha + rsum;
            m_i[i] = mnew;
#pragma unroll
            for (int j = 0; j < 4; ++j) acc[i][j] *= alpha;
            *(float4*)&Ps[(ty*4+i)*64 + tx*4] = make_float4(s[i][0],s[i][1],s[i][2],s[i][3]);
        }
        __syncthreads();   // P complete; K reads done -> KVs reusable

        // load V tile natural: KVs[key][d]
        {
            int r  = tid >> 2;
            int c0 = (tid & 3) * 16;
            const float* src = Vbase + (size_t)(k0 + r) * NKV_ * D_;
#pragma unroll
            for (int c = 0; c < 16; c += 4)
                *(float4*)&KVs[r*64 + c0 + c] = *(const float4*)(src + c0 + c);
        }
        __syncthreads();

        // O += P V  (64x64x64), kk unrolled by 4
        for (int kk = 0; kk < 64; kk += 4) {
            float4 vb0 = *(const float4*)&KVs[(kk+0)*64 + tx*4];
            float4 vb1 = *(const float4*)&KVs[(kk+1)*64 + tx*4];
            float4 vb2 = *(const float4*)&KVs[(kk+2)*64 + tx*4];
            float4 vb3 = *(const float4*)&KVs[(kk+3)*64 + tx*4];
#pragma unroll
            for (int i = 0; i < 4; ++i) {
                float4 p = *(const float4*)&Ps[(ty*4+i)*64 + kk];
                acc[i][0] = fmaf(p.x, vb0.x, acc[i][0]);
                acc[i][1] = fmaf(p.x, vb0.y, acc[i][1]);
                acc[i][2] = fmaf(p.x, vb0.z, acc[i][2]);
                acc[i][3] = fmaf(p.x, vb0.w, acc[i][3]);
                acc[i][0] = fmaf(p.y, vb1.x, acc[i][0]);
                acc[i][1] = fmaf(p.y, vb1.y, acc[i][1]);
                acc[i][2] = fmaf(p.y, vb1.z, acc[i][2]);
                acc[i][3] = fmaf(p.y, vb1.w, acc[i][3]);
                acc[i][0] = fmaf(p.z, vb2.x, acc[i][0]);
                acc[i][1] = fmaf(p.z, vb2.y, acc[i][1]);
                acc[i][2] = fmaf(p.z, vb2.z, acc[i][2]);
                acc[i][3] = fmaf(p.z, vb2.w, acc[i][3]);
                acc[i][0] = fmaf(p.w, vb3.x, acc[i][0]);
                acc[i][1] = fmaf(p.w, vb3.y, acc[i][1]);
                acc[i][2] = fmaf(p.w, vb3.z, acc[i][2]);
                acc[i][3] = fmaf(p.w, vb3.w, acc[i][3]);
            }
        }
    }

    // finalize and store: O[(b*S + qrow)][h*64 + d]
#pragma unroll
    for (int i = 0; i < 4; ++i) {
        float inv = 1.f / l_i[i];
        float* dst = O + (size_t)(b*S_ + q0 + ty*4 + i) * NH_ * D_ + (size_t)h * D_ + tx*4;
        *(float4*)dst = make_float4(acc[i][0]*inv, acc[i][1]*inv, acc[i][2]*inv, acc[i][3]*inv);
    }
}

// ---------------- launch ------------------------------------------------------
extern "C" void kernel_launch(void* const* d_in, const int* in_sizes, int n_in,
                              void* d_out, int out_size)
{
    const float* x    = (const float*)d_in[0];
    const float* cosb = (const float*)d_in[1];
    const float* sinb = (const float*)d_in[2];
    // d_in[3] = mask (causal tril; structure hard-coded)
    const float* wq   = (const float*)d_in[4];
    const float* wk   = (const float*)d_in[5];
    const float* wv   = (const float*)d_in[6];
    const float* wo   = (const float*)d_in[7];
    float* out = (float*)d_out;

    float *q, *k, *v, *o;
    cudaGetSymbolAddress((void**)&q, g_q);
    cudaGetSymbolAddress((void**)&k, g_k);
    cudaGetSymbolAddress((void**)&v, g_v);
    cudaGetSymbolAddress((void**)&o, g_o);

    const int M = B_ * S_;  // 4096

    dim3 gq(NH_*D_/128,  M/128);   // (16,32)
    dim3 gk(NKV_*D_/128, M/128);   // (4,32)
    sgemm_tn<<<gq, 256>>>(x, wq, q, M, NH_*D_,  H_);
    sgemm_tn<<<gk, 256>>>(x, wk, k, M, NKV_*D_, H_);
    sgemm_tn<<<gk, 256>>>(x, wv, v, M, NKV_*D_, H_);

    int tq = B_*S_*NH_ *(D_/2);
    int tk = B_*S_*NKV_*(D_/2);
    rope_kernel<<<(tq+255)/256, 256>>>(q, cosb, sinb, NH_);
    rope_kernel<<<(tk+255)/256, 256>>>(k, cosb, sinb, NKV_);

    dim3 gf(S_/64, B_*NH_);        // (32, 64)
    flash_kernel<<<gf, 256>>>(q, k, v, o);

    sgemm_tn<<<gq, 256>>>(o, wo, out, M, H_, NH_*D_);
}

// round 4
// speedup vs baseline: 2.9180x; 2.9180x over previous
#include <cuda_runtime.h>
#include <cstdint>
#include <math.h>

#define B_    2
#define S_    2048
#define H_    2048
#define NH_   32
#define NKV_  8
#define D_    64
#define GROUPS_ (NH_/NKV_)
#define SCALE_ 0.125f   // D^-0.5

// ---------------- scratch (device globals; no allocs allowed) ----------------
__device__ float g_q[(size_t)B_*S_*NH_*D_];
__device__ float g_k[(size_t)B_*S_*NKV_*D_];
__device__ float g_v[(size_t)B_*S_*NKV_*D_];
__device__ float g_o[(size_t)B_*S_*NH_*D_];

// ---------------- tf32 / mma helpers -----------------------------------------
__device__ __forceinline__ uint32_t f2tf(float f) {
    uint32_t u;
    asm("cvt.rna.tf32.f32 %0, %1;" : "=r"(u) : "f"(f));
    return u;
}
__device__ __forceinline__ float f2tff(float f) { return __uint_as_float(f2tf(f)); }

__device__ __forceinline__ void ldm4(uint32_t& r0, uint32_t& r1, uint32_t& r2, uint32_t& r3,
                                     uint32_t addr) {
    asm volatile("ldmatrix.sync.aligned.m8n8.x4.shared.b16 {%0,%1,%2,%3}, [%4];"
                 : "=r"(r0), "=r"(r1), "=r"(r2), "=r"(r3) : "r"(addr));
}

__device__ __forceinline__ void mma_tf32(float& c0, float& c1, float& c2, float& c3,
                                         uint32_t a0, uint32_t a1, uint32_t a2, uint32_t a3,
                                         uint32_t b0, uint32_t b1) {
    asm volatile(
        "mma.sync.aligned.m16n8k8.row.col.f32.tf32.tf32.f32 "
        "{%0,%1,%2,%3},{%4,%5,%6,%7},{%8,%9},{%0,%1,%2,%3};"
        : "+f"(c0), "+f"(c1), "+f"(c2), "+f"(c3)
        : "r"(a0), "r"(a1), "r"(a2), "r"(a3), "r"(b0), "r"(b1));
}

// ---------------- tf32 GEMM: C[M,N] = A[M,K] * W[N,K]^T ----------------------
// 128x128x32 tiles, 256 threads (8 warps, 2x4), warp tile 64x32.
#define ASTR 36   // 32 + 4 pad (floats); 144B row stride -> conflict-free ldmatrix

__global__ void __launch_bounds__(256) gemm_tf32(
    const float* __restrict__ A, const float* __restrict__ W,
    float* __restrict__ C, int M, int N, int K)
{
    __shared__ float As[128 * ASTR];
    __shared__ float Bs[128 * ASTR];

    const int tid  = threadIdx.x;
    const int warp = tid >> 5, lane = tid & 31;
    const int gid  = lane >> 2, tig = lane & 3;
    const int wm   = warp >> 2, wn = warp & 3;
    const int bm   = blockIdx.y * 128, bn = blockIdx.x * 128;

    const int srow = tid >> 3;            // 0..31 (+32*i)
    const int sc4  = (tid & 7) * 4;       // 0,4,...,28

    const float* Ag = A + (size_t)bm * K;
    const float* Wg = W + (size_t)bn * K;

    float acc[4][4][4];
#pragma unroll
    for (int mt = 0; mt < 4; ++mt)
#pragma unroll
        for (int nf = 0; nf < 4; ++nf)
#pragma unroll
            for (int r = 0; r < 4; ++r) acc[mt][nf][r] = 0.f;

    const uint32_t sA = (uint32_t)__cvta_generic_to_shared(As);
    const uint32_t sB = (uint32_t)__cvta_generic_to_shared(Bs);

    float4 ra[4], rb[4];
#pragma unroll
    for (int i = 0; i < 4; ++i) {
        ra[i] = *(const float4*)(Ag + (size_t)(srow + 32 * i) * K + sc4);
        rb[i] = *(const float4*)(Wg + (size_t)(srow + 32 * i) * K + sc4);
    }

    for (int k0 = 0; k0 < K; k0 += 32) {
        // store staged tile (with tf32 convert)
#pragma unroll
        for (int i = 0; i < 4; ++i) {
            float* pa = &As[(srow + 32 * i) * ASTR + sc4];
            pa[0] = f2tff(ra[i].x); pa[1] = f2tff(ra[i].y);
            pa[2] = f2tff(ra[i].z); pa[3] = f2tff(ra[i].w);
            float* pb = &Bs[(srow + 32 * i) * ASTR + sc4];
            pb[0] = f2tff(rb[i].x); pb[1] = f2tff(rb[i].y);
            pb[2] = f2tff(rb[i].z); pb[3] = f2tff(rb[i].w);
        }
        __syncthreads();

        if (k0 + 32 < K) {
#pragma unroll
            for (int i = 0; i < 4; ++i) {
                ra[i] = *(const float4*)(Ag + (size_t)(srow + 32 * i) * K + k0 + 32 + sc4);
                rb[i] = *(const float4*)(Wg + (size_t)(srow + 32 * i) * K + k0 + 32 + sc4);
            }
        }

#pragma unroll
        for (int kk = 0; kk < 32; kk += 8) {
            uint32_t af[4][4];
#pragma unroll
            for (int mt = 0; mt < 4; ++mt) {
                int row = wm * 64 + mt * 16 + (lane & 15);
                int col = kk + (lane >> 4) * 4;
                ldm4(af[mt][0], af[mt][1], af[mt][2], af[mt][3],
                     sA + (uint32_t)((row * ASTR + col) * 4));
            }
            uint32_t bf[2][4];
#pragma unroll
            for (int bt = 0; bt < 2; ++bt) {
                int nrow = wn * 32 + bt * 16 + ((lane >> 4) << 3) + (lane & 7);
                int col  = kk + ((lane >> 3) & 1) * 4;
                ldm4(bf[bt][0], bf[bt][1], bf[bt][2], bf[bt][3],
                     sB + (uint32_t)((nrow * ASTR + col) * 4));
            }
#pragma unroll
            for (int mt = 0; mt < 4; ++mt)
#pragma unroll
                for (int nf = 0; nf < 4; ++nf) {
                    int bt = nf >> 1, hi = (nf & 1) * 2;
                    mma_tf32(acc[mt][nf][0], acc[mt][nf][1], acc[mt][nf][2], acc[mt][nf][3],
                             af[mt][0], af[mt][1], af[mt][2], af[mt][3],
                             bf[bt][hi], bf[bt][hi + 1]);
                }
        }
        __syncthreads();
    }

#pragma unroll
    for (int mt = 0; mt < 4; ++mt)
#pragma unroll
        for (int nf = 0; nf < 4; ++nf) {
            int row = bm + wm * 64 + mt * 16 + gid;
            int col = bn + wn * 32 + nf * 8 + tig * 2;
            *(float2*)(C + (size_t)row * N + col) =
                make_float2(acc[mt][nf][0], acc[mt][nf][1]);
            *(float2*)(C + (size_t)(row + 8) * N + col) =
                make_float2(acc[mt][nf][2], acc[mt][nf][3]);
        }
}

// ---------------- RoPE (in-place, paired halves) ------------------------------
__global__ void rope_kernel(float* __restrict__ buf,
                            const float* __restrict__ cosb,
                            const float* __restrict__ sinb,
                            int nheads)
{
    int idx = blockIdx.x * blockDim.x + threadIdx.x;
    int total = B_ * S_ * nheads * (D_ / 2);
    if (idx >= total) return;
    int d   = idx % (D_ / 2);
    int h   = (idx / (D_ / 2)) % nheads;
    int row = idx / ((D_ / 2) * nheads);
    size_t base = (size_t)row * nheads * D_ + (size_t)h * D_;
    float q1 = buf[base + d];
    float q2 = buf[base + d + D_ / 2];
    float c1 = cosb[(size_t)row * D_ + d];
    float c2 = cosb[(size_t)row * D_ + d + D_ / 2];
    float s1 = sinb[(size_t)row * D_ + d];
    float s2 = sinb[(size_t)row * D_ + d + D_ / 2];
    buf[base + d]          = q1 * c1 - q2 * s1;
    buf[base + d + D_ / 2] = q2 * c2 + q1 * s2;
}

// ---------------- tf32 flash attention (causal, GQA) --------------------------
// 64 q-rows/block, 4 warps, warp = m16 strip. S and PV both via mma.
#define FSTR 68                               // floats; 272B stride (16B aligned, conflict-free ldmatrix)
#define FLASH_SMEM (3 * 64 * FSTR * 4)        // PQ + Ks + Vt = 52224 B

__global__ void __launch_bounds__(128) flash_tf32(
    const float* __restrict__ Q, const float* __restrict__ K,
    const float* __restrict__ V, float* __restrict__ O)
{
    extern __shared__ float sm[];
    float* PQ = sm;                 // [64][FSTR]  Q tile, then P tile
    float* Ks = sm + 64 * FSTR;     // [key][d]
    float* Vt = sm + 2 * 64 * FSTR; // [d][key], chunk-XOR swizzled

    const int tid  = threadIdx.x;
    const int warp = tid >> 5, lane = tid & 31;
    const int gid  = lane >> 2, tig = lane & 3;
    const int qt = blockIdx.x, bh = blockIdx.y;
    const int b  = bh >> 5, h = bh & 31;
    const int kvh = h >> 2;
    const int q0 = qt * 64;

    const float* Qb = Q + (size_t)b * S_ * NH_  * D_ + (size_t)h   * D_;
    const float* Kb = K + (size_t)b * S_ * NKV_ * D_ + (size_t)kvh * D_;
    const float* Vb = V + (size_t)b * S_ * NKV_ * D_ + (size_t)kvh * D_;

    const uint32_t sPQ = (uint32_t)__cvta_generic_to_shared(PQ);
    const uint32_t sKs = (uint32_t)__cvta_generic_to_shared(Ks);
    const uint32_t sVt = (uint32_t)__cvta_generic_to_shared(Vt);

    // stage Q (tf32) -> PQ
#pragma unroll
    for (int i = 0; i < 8; ++i) {
        int idx = tid + i * 128;
        int r = idx >> 4, c4 = (idx & 15) * 4;
        float4 v = *(const float4*)(Qb + (size_t)(q0 + r) * (NH_ * D_) + c4);
        float* p = &PQ[r * FSTR + c4];
        p[0] = f2tff(v.x); p[1] = f2tff(v.y); p[2] = f2tff(v.z); p[3] = f2tff(v.w);
    }
    __syncthreads();

    // preload Q fragments (warp's own 16-row strip, k = 0..63)
    uint32_t qf[8][4];
#pragma unroll
    for (int kk8 = 0; kk8 < 8; ++kk8) {
        int row = warp * 16 + (lane & 15);
        int col = kk8 * 8 + (lane >> 4) * 4;
        ldm4(qf[kk8][0], qf[kk8][1], qf[kk8][2], qf[kk8][3],
             sPQ + (uint32_t)((row * FSTR + col) * 4));
    }

    float oacc[8][4];
#pragma unroll
    for (int nf = 0; nf < 8; ++nf)
#pragma unroll
        for (int r = 0; r < 4; ++r) oacc[nf][r] = 0.f;
    float mrow[2] = {-1e30f, -1e30f}, lrow[2] = {0.f, 0.f};

    for (int t = 0; t <= qt; ++t) {
        const int k0 = t * 64;
        __syncthreads();   // Ks/Vt safe to overwrite (covers qf preload at t=0)

        // stage K tile: Ks[key][d]
#pragma unroll
        for (int i = 0; i < 8; ++i) {
            int idx = tid + i * 128;
            int r = idx >> 4, c4 = (idx & 15) * 4;
            float4 v = *(const float4*)(Kb + (size_t)(k0 + r) * (NKV_ * D_) + c4);
            float* p = &Ks[r * FSTR + c4];
            p[0] = f2tff(v.x); p[1] = f2tff(v.y); p[2] = f2tff(v.z); p[3] = f2tff(v.w);
        }
        // stage V transposed: Vt[d][key], 16B-chunk XOR swizzle on key
#pragma unroll
        for (int i = 0; i < 8; ++i) {
            int idx = tid + i * 128;
            int r = idx >> 4, c4 = idx & 15;     // r = key, d = 4*c4 + j
            float4 v = *(const float4*)(Vb + (size_t)(k0 + r) * (NKV_ * D_) + c4 * 4);
            int kc = r >> 2, kr = r & 3;
            float vv[4] = {v.x, v.y, v.z, v.w};
#pragma unroll
            for (int j = 0; j < 4; ++j) {
                int d = c4 * 4 + j;
                Vt[d * FSTR + (((kc ^ ((d >> 2) & 3)) << 2) | kr)] = f2tff(vv[j]);
            }
        }
        __syncthreads();

        // S = Q K^T (warp: 16 x 64)
        float sacc[8][4];
#pragma unroll
        for (int nf = 0; nf < 8; ++nf)
#pragma unroll
            for (int r = 0; r < 4; ++r) sacc[nf][r] = 0.f;

#pragma unroll
        for (int kk8 = 0; kk8 < 8; ++kk8) {
            uint32_t bfr[4][4];
#pragma unroll
            for (int bt = 0; bt < 4; ++bt) {
                int nrow = bt * 16 + ((lane >> 4) << 3) + (lane & 7);
                int col  = kk8 * 8 + ((lane >> 3) & 1) * 4;
                ldm4(bfr[bt][0], bfr[bt][1], bfr[bt][2], bfr[bt][3],
                     sKs + (uint32_t)((nrow * FSTR + col) * 4));
            }
#pragma unroll
            for (int nf = 0; nf < 8; ++nf) {
                int bt = nf >> 1, hi = (nf & 1) * 2;
                mma_tf32(sacc[nf][0], sacc[nf][1], sacc[nf][2], sacc[nf][3],
                         qf[kk8][0], qf[kk8][1], qf[kk8][2], qf[kk8][3],
                         bfr[bt][hi], bfr[bt][hi + 1]);
            }
        }

        // online softmax per row-half (rows gid, gid+8 of warp strip)
#pragma unroll
        for (int hh = 0; hh < 2; ++hh) {
            int row = q0 + warp * 16 + gid + hh * 8;
            float mloc = -1e30f;
#pragma unroll
            for (int nf = 0; nf < 8; ++nf) {
                float s0 = sacc[nf][hh * 2]     * SCALE_;
                float s1 = sacc[nf][hh * 2 + 1] * SCALE_;
                if (t == qt) {
                    int col = k0 + nf * 8 + tig * 2;
                    if (col     > row) s0 = -1e30f;
                    if (col + 1 > row) s1 = -1e30f;
                }
                sacc[nf][hh * 2] = s0; sacc[nf][hh * 2 + 1] = s1;
                mloc = fmaxf(mloc, fmaxf(s0, s1));
            }
            mloc = fmaxf(mloc, __shfl_xor_sync(0xffffffffu, mloc, 1));
            mloc = fmaxf(mloc, __shfl_xor_sync(0xffffffffu, mloc, 2));
            float mnew  = fmaxf(mrow[hh], mloc);
            float alpha = __expf(mrow[hh] - mnew);
            mrow[hh] = mnew;
            float rs = 0.f;
#pragma unroll
            for (int nf = 0; nf < 8; ++nf) {
                float p0 = __expf(sacc[nf][hh * 2]     - mnew);
                float p1 = __expf(sacc[nf][hh * 2 + 1] - mnew);
                sacc[nf][hh * 2] = p0; sacc[nf][hh * 2 + 1] = p1;
                rs += p0 + p1;
            }
            rs += __shfl_xor_sync(0xffffffffu, rs, 1);
            rs += __shfl_xor_sync(0xffffffffu, rs, 2);
            lrow[hh] = lrow[hh] * alpha + rs;
#pragma unroll
            for (int nf = 0; nf < 8; ++nf) {
                oacc[nf][hh * 2]     *= alpha;
                oacc[nf][hh * 2 + 1] *= alpha;
            }
            // write P (tf32) into PQ (warp-private rows)
            int prow = warp * 16 + gid + hh * 8;
#pragma unroll
            for (int nf = 0; nf < 8; ++nf) {
                *(float2*)&PQ[prow * FSTR + nf * 8 + tig * 2] =
                    make_float2(f2tff(sacc[nf][hh * 2]), f2tff(sacc[nf][hh * 2 + 1]));
            }
        }
        __syncwarp();

        // O += P V  (k = key 0..63, n = d 0..63)
#pragma unroll
        for (int kk8 = 0; kk8 < 8; ++kk8) {
            uint32_t pf[4];
            {
                int row = warp * 16 + (lane & 15);
                int col = kk8 * 8 + (lane >> 4) * 4;
                ldm4(pf[0], pf[1], pf[2], pf[3],
                     sPQ + (uint32_t)((row * FSTR + col) * 4));
            }
            uint32_t vfr[4][4];
#pragma unroll
            for (int bt = 0; bt < 4; ++bt) {
                int d  = bt * 16 + ((lane >> 4) << 3) + (lane & 7);
                int kc = kk8 * 2 + ((lane >> 3) & 1);
                uint32_t addr = sVt +
                    (uint32_t)((d * FSTR + ((kc ^ ((d >> 2) & 3)) << 2)) * 4);
                ldm4(vfr[bt][0], vfr[bt][1], vfr[bt][2], vfr[bt][3], addr);
            }
#pragma unroll
            for (int nf = 0; nf < 8; ++nf) {
                int bt = nf >> 1, hi = (nf & 1) * 2;
                mma_tf32(oacc[nf][0], oacc[nf][1], oacc[nf][2], oacc[nf][3],
                         pf[0], pf[1], pf[2], pf[3],
                         vfr[bt][hi], vfr[bt][hi + 1]);
            }
        }
    }

    // epilogue: O[(b*S+row)][h*64 + col]
#pragma unroll
    for (int hh = 0; hh < 2; ++hh) {
        int row = q0 + warp * 16 + gid + hh * 8;
        float inv = 1.f / lrow[hh];
#pragma unroll
        for (int nf = 0; nf < 8; ++nf) {
            *(float2*)(O + (size_t)(b * S_ + row) * (NH_ * D_) + h * D_ + nf * 8 + tig * 2) =
                make_float2(oacc[nf][hh * 2] * inv, oacc[nf][hh * 2 + 1] * inv);
        }
    }
}

// ---------------- launch ------------------------------------------------------
extern "C" void kernel_launch(void* const* d_in, const int* in_sizes, int n_in,
                              void* d_out, int out_size)
{
    const float* x    = (const float*)d_in[0];
    const float* cosb = (const float*)d_in[1];
    const float* sinb = (const float*)d_in[2];
    // d_in[3] = causal mask (structure hard-coded)
    const float* wq   = (const float*)d_in[4];
    const float* wk   = (const float*)d_in[5];
    const float* wv   = (const float*)d_in[6];
    const float* wo   = (const float*)d_in[7];
    float* out = (float*)d_out;

    float *q, *k, *v, *o;
    cudaGetSymbolAddress((void**)&q, g_q);
    cudaGetSymbolAddress((void**)&k, g_k);
    cudaGetSymbolAddress((void**)&v, g_v);
    cudaGetSymbolAddress((void**)&o, g_o);

    cudaFuncSetAttribute(flash_tf32, cudaFuncAttributeMaxDynamicSharedMemorySize, FLASH_SMEM);

    const int M = B_ * S_;  // 4096

    dim3 gq(NH_ * D_ / 128, M / 128);    // (16,32)
    dim3 gk(NKV_ * D_ / 128, M / 128);   // (4,32)
    gemm_tf32<<<gq, 256>>>(x, wq, q, M, NH_ * D_,  H_);
    gemm_tf32<<<gk, 256>>>(x, wk, k, M, NKV_ * D_, H_);
    gemm_tf32<<<gk, 256>>>(x, wv, v, M, NKV_ * D_, H_);

    int tq = B_ * S_ * NH_  * (D_ / 2);
    int tk = B_ * S_ * NKV_ * (D_ / 2);
    rope_kernel<<<(tq + 255) / 256, 256>>>(q, cosb, sinb, NH_);
    rope_kernel<<<(tk + 255) / 256, 256>>>(k, cosb, sinb, NKV_);

    dim3 gf(S_ / 64, B_ * NH_);          // (32, 64)
    flash_tf32<<<gf, 128, FLASH_SMEM>>>(q, k, v, o);

    gemm_tf32<<<gq, 256>>>(o, wo, out, M, H_, NH_ * D_);
}

// round 5
// speedup vs baseline: 3.7117x; 1.2720x over previous
#include <cuda_runtime.h>
#include <cstdint>
#include <math.h>

#define B_    2
#define S_    2048
#define H_    2048
#define NH_   32
#define NKV_  8
#define D_    64
#define SCALE_ 0.125f   // D^-0.5

// ---------------- scratch (device globals; no allocs allowed) ----------------
__device__ float g_q[(size_t)B_*S_*NH_*D_];
__device__ float g_k[(size_t)B_*S_*NKV_*D_];
__device__ float g_v[(size_t)B_*S_*NKV_*D_];
__device__ float g_o[(size_t)B_*S_*NH_*D_];
__device__ float g_xc[(size_t)B_*S_*H_];       // tf32-rounded x
__device__ float g_wqc[(size_t)NH_*D_*H_];
__device__ float g_wkc[(size_t)NKV_*D_*H_];
__device__ float g_wvc[(size_t)NKV_*D_*H_];
__device__ float g_woc[(size_t)H_*NH_*D_];

// ---------------- helpers -----------------------------------------------------
__device__ __forceinline__ uint32_t f2tf(float f) {
    uint32_t u;
    asm("cvt.rna.tf32.f32 %0, %1;" : "=r"(u) : "f"(f));
    return u;
}
__device__ __forceinline__ float f2tff(float f) { return __uint_as_float(f2tf(f)); }

__device__ __forceinline__ void cp16(uint32_t smem, const void* gmem) {
    asm volatile("cp.async.cg.shared.global [%0], [%1], 16;" :: "r"(smem), "l"(gmem));
}
__device__ __forceinline__ void cp_commit() {
    asm volatile("cp.async.commit_group;" ::: "memory");
}

__device__ __forceinline__ void ldm4(uint32_t& r0, uint32_t& r1, uint32_t& r2, uint32_t& r3,
                                     uint32_t addr) {
    asm volatile("ldmatrix.sync.aligned.m8n8.x4.shared.b16 {%0,%1,%2,%3}, [%4];"
                 : "=r"(r0), "=r"(r1), "=r"(r2), "=r"(r3) : "r"(addr));
}

__device__ __forceinline__ void mma_tf32(float& c0, float& c1, float& c2, float& c3,
                                         uint32_t a0, uint32_t a1, uint32_t a2, uint32_t a3,
                                         uint32_t b0, uint32_t b1) {
    asm volatile(
        "mma.sync.aligned.m16n8k8.row.col.f32.tf32.tf32.f32 "
        "{%0,%1,%2,%3},{%4,%5,%6,%7},{%8,%9},{%0,%1,%2,%3};"
        : "+f"(c0), "+f"(c1), "+f"(c2), "+f"(c3)
        : "r"(a0), "r"(a1), "r"(a2), "r"(a3), "r"(b0), "r"(b1));
}

// ---------------- tf32 pre-round kernel ---------------------------------------
__global__ void cvt_kernel(float* __restrict__ dst, const float* __restrict__ src, int n4) {
    int i = blockIdx.x * blockDim.x + threadIdx.x;
    if (i >= n4) return;
    float4 v = ((const float4*)src)[i];
    ((float4*)dst)[i] = make_float4(f2tff(v.x), f2tff(v.y), f2tff(v.z), f2tff(v.w));
}

// ---------------- tf32 GEMM: C[M,N] = A[M,K] * W[N,K]^T -----------------------
// Inputs pre-rounded to tf32. 128x128x32 tiles, 3-stage cp.async pipeline.
#define ASTR 36
#define STAGES 3
#define GEMM_SMEM (STAGES * 2 * 128 * ASTR * 4)   // 110592 B

__global__ void __launch_bounds__(256) gemm_tf32(
    const float* __restrict__ A, const float* __restrict__ W,
    float* __restrict__ C, int M, int N, int K, int round_out)
{
    extern __shared__ float sm[];
    float* As = sm;                           // [STAGES][128*ASTR]
    float* Bs = sm + STAGES * 128 * ASTR;

    const int tid  = threadIdx.x;
    const int warp = tid >> 5, lane = tid & 31;
    const int gid  = lane >> 2, tig = lane & 3;
    const int wm   = warp >> 2, wn = warp & 3;
    const int bm   = blockIdx.y * 128, bn = blockIdx.x * 128;

    const int srow = tid >> 3;          // 0..31 (+32*i)
    const int sc4  = (tid & 7) * 4;

    const float* Ag = A + (size_t)bm * K;
    const float* Wg = W + (size_t)bn * K;

    const uint32_t sA = (uint32_t)__cvta_generic_to_shared(As);
    const uint32_t sB = (uint32_t)__cvta_generic_to_shared(Bs);

    float acc[4][4][4];
#pragma unroll
    for (int mt = 0; mt < 4; ++mt)
#pragma unroll
        for (int nf = 0; nf < 4; ++nf)
#pragma unroll
            for (int r = 0; r < 4; ++r) acc[mt][nf][r] = 0.f;

    auto issue = [&](int st, int k0) {
        uint32_t baseA = sA + (uint32_t)(st * 128 * ASTR * 4);
        uint32_t baseB = sB + (uint32_t)(st * 128 * ASTR * 4);
#pragma unroll
        for (int i = 0; i < 4; ++i) {
            int row = srow + 32 * i;
            cp16(baseA + (uint32_t)((row * ASTR + sc4) * 4),
                 Ag + (size_t)row * K + k0 + sc4);
            cp16(baseB + (uint32_t)((row * ASTR + sc4) * 4),
                 Wg + (size_t)row * K + k0 + sc4);
        }
        cp_commit();
    };

    const int nk = K / 32;
    issue(0, 0);
    issue(1, 32);

    for (int it = 0; it < nk; ++it) {
        if (it + 1 < nk) { asm volatile("cp.async.wait_group 1;" ::: "memory"); }
        else             { asm volatile("cp.async.wait_group 0;" ::: "memory"); }
        __syncthreads();

        if (it + 2 < nk) issue((it + 2) % STAGES, (it + 2) * 32);

        const int st  = it % STAGES;
        const uint32_t aBase = sA + (uint32_t)(st * 128 * ASTR * 4);
        const uint32_t bBase = sB + (uint32_t)(st * 128 * ASTR * 4);

#pragma unroll
        for (int kk = 0; kk < 32; kk += 8) {
            uint32_t af[4][4];
#pragma unroll
            for (int mt = 0; mt < 4; ++mt) {
                int row = wm * 64 + mt * 16 + (lane & 15);
                int col = kk + (lane >> 4) * 4;
                ldm4(af[mt][0], af[mt][1], af[mt][2], af[mt][3],
                     aBase + (uint32_t)((row * ASTR + col) * 4));
            }
            uint32_t bf[2][4];
#pragma unroll
            for (int bt = 0; bt < 2; ++bt) {
                int nrow = wn * 32 + bt * 16 + ((lane >> 4) << 3) + (lane & 7);
                int col  = kk + ((lane >> 3) & 1) * 4;
                ldm4(bf[bt][0], bf[bt][1], bf[bt][2], bf[bt][3],
                     bBase + (uint32_t)((nrow * ASTR + col) * 4));
            }
#pragma unroll
            for (int mt = 0; mt < 4; ++mt)
#pragma unroll
                for (int nf = 0; nf < 4; ++nf) {
                    int bt = nf >> 1, hi = (nf & 1) * 2;
                    mma_tf32(acc[mt][nf][0], acc[mt][nf][1], acc[mt][nf][2], acc[mt][nf][3],
                             af[mt][0], af[mt][1], af[mt][2], af[mt][3],
                             bf[bt][hi], bf[bt][hi + 1]);
                }
        }
    }

#pragma unroll
    for (int mt = 0; mt < 4; ++mt)
#pragma unroll
        for (int nf = 0; nf < 4; ++nf) {
            int row = bm + wm * 64 + mt * 16 + gid;
            int col = bn + wn * 32 + nf * 8 + tig * 2;
            float v0 = acc[mt][nf][0], v1 = acc[mt][nf][1];
            float v2 = acc[mt][nf][2], v3 = acc[mt][nf][3];
            if (round_out) { v0 = f2tff(v0); v1 = f2tff(v1); v2 = f2tff(v2); v3 = f2tff(v3); }
            *(float2*)(C + (size_t)row * N + col)       = make_float2(v0, v1);
            *(float2*)(C + (size_t)(row + 8) * N + col) = make_float2(v2, v3);
        }
}

// ---------------- RoPE (in-place, writes tf32-rounded) ------------------------
__global__ void rope_kernel(float* __restrict__ buf,
                            const float* __restrict__ cosb,
                            const float* __restrict__ sinb,
                            int nheads)
{
    int idx = blockIdx.x * blockDim.x + threadIdx.x;
    int total = B_ * S_ * nheads * (D_ / 2);
    if (idx >= total) return;
    int d   = idx % (D_ / 2);
    int h   = (idx / (D_ / 2)) % nheads;
    int row = idx / ((D_ / 2) * nheads);
    size_t base = (size_t)row * nheads * D_ + (size_t)h * D_;
    float q1 = buf[base + d];
    float q2 = buf[base + d + D_ / 2];
    float c1 = cosb[(size_t)row * D_ + d];
    float c2 = cosb[(size_t)row * D_ + d + D_ / 2];
    float s1 = sinb[(size_t)row * D_ + d];
    float s2 = sinb[(size_t)row * D_ + d + D_ / 2];
    buf[base + d]          = f2tff(q1 * c1 - q2 * s1);
    buf[base + d + D_ / 2] = f2tff(q2 * c2 + q1 * s2);
}

// ---------------- tf32 flash attention (causal, GQA) --------------------------
// 64 q-rows/block, 4 warps. K/V tiles double-buffered via cp.async.
#define FSTR  68
#define FSTRV 72
#define FLASH_SMEM ((64 * FSTR + 2 * 64 * FSTR + 2 * 64 * FSTRV) * 4)   // 89088 B

__global__ void __launch_bounds__(128) flash_tf32(
    const float* __restrict__ Q, const float* __restrict__ K,
    const float* __restrict__ V, float* __restrict__ O)
{
    extern __shared__ float sm[];
    float* PQ = sm;                         // [64][FSTR]   Q tile then P tile
    float* Ks = sm + 64 * FSTR;             // [2][64][FSTR]
    float* Vs = sm + 3 * 64 * FSTR;         // [2][64][FSTRV] natural [key][d]

    const int tid  = threadIdx.x;
    const int warp = tid >> 5, lane = tid & 31;
    const int gid  = lane >> 2, tig = lane & 3;
    const int qt = blockIdx.x, bh = blockIdx.y;
    const int b  = bh >> 5, h = bh & 31;
    const int kvh = h >> 2;
    const int q0 = qt * 64;

    const float* Qb = Q + (size_t)b * S_ * NH_  * D_ + (size_t)h   * D_;
    const float* Kb = K + (size_t)b * S_ * NKV_ * D_ + (size_t)kvh * D_;
    const float* Vb = V + (size_t)b * S_ * NKV_ * D_ + (size_t)kvh * D_;

    const uint32_t sPQ = (uint32_t)__cvta_generic_to_shared(PQ);
    const uint32_t sKs = (uint32_t)__cvta_generic_to_shared(Ks);
    const uint32_t sVs = (uint32_t)__cvta_generic_to_shared(Vs);

    const int cr  = tid >> 4;           // 0..7  (+8*i)
    const int cc4 = (tid & 15) * 4;     // 0..60

    auto issue_kv = [&](int t, int buf) {
        const int k0 = t * 64;
#pragma unroll
        for (int i = 0; i < 8; ++i) {
            int r = cr + 8 * i;
            cp16(sKs + (uint32_t)(((buf * 64 + r) * FSTR  + cc4) * 4),
                 Kb + (size_t)(k0 + r) * (NKV_ * D_) + cc4);
            cp16(sVs + (uint32_t)(((buf * 64 + r) * FSTRV + cc4) * 4),
                 Vb + (size_t)(k0 + r) * (NKV_ * D_) + cc4);
        }
        cp_commit();
    };

    // Q -> PQ (group 0), KV tile 0 (group 1)
#pragma unroll
    for (int i = 0; i < 8; ++i) {
        int r = cr + 8 * i;
        cp16(sPQ + (uint32_t)((r * FSTR + cc4) * 4),
             Qb + (size_t)(q0 + r) * (NH_ * D_) + cc4);
    }
    cp_commit();
    issue_kv(0, 0);

    asm volatile("cp.async.wait_group 1;" ::: "memory");   // Q ready
    __syncthreads();

    uint32_t qf[8][4];
#pragma unroll
    for (int kk8 = 0; kk8 < 8; ++kk8) {
        int row = warp * 16 + (lane & 15);
        int col = kk8 * 8 + (lane >> 4) * 4;
        ldm4(qf[kk8][0], qf[kk8][1], qf[kk8][2], qf[kk8][3],
             sPQ + (uint32_t)((row * FSTR + col) * 4));
    }

    float oacc[8][4];
#pragma unroll
    for (int nf = 0; nf < 8; ++nf)
#pragma unroll
        for (int r = 0; r < 4; ++r) oacc[nf][r] = 0.f;
    float mrow[2] = {-1e30f, -1e30f}, lrow[2] = {0.f, 0.f};

    for (int t = 0; t <= qt; ++t) {
        const int k0  = t * 64;
        const int buf = t & 1;

        asm volatile("cp.async.wait_group 0;" ::: "memory");
        __syncthreads();
        if (t < qt) issue_kv(t + 1, buf ^ 1);   // overlaps with this tile's compute

        const uint32_t kBase = sKs + (uint32_t)(buf * 64 * FSTR  * 4);
        const int      vRow0 = buf * 64;

        // ---- S = Q K^T ----
        float sacc[8][4];
#pragma unroll
        for (int nf = 0; nf < 8; ++nf)
#pragma unroll
            for (int r = 0; r < 4; ++r) sacc[nf][r] = 0.f;

#pragma unroll
        for (int kk8 = 0; kk8 < 8; ++kk8) {
            uint32_t bfr[4][4];
#pragma unroll
            for (int bt = 0; bt < 4; ++bt) {
                int nrow = bt * 16 + ((lane >> 4) << 3) + (lane & 7);
                int col  = kk8 * 8 + ((lane >> 3) & 1) * 4;
                ldm4(bfr[bt][0], bfr[bt][1], bfr[bt][2], bfr[bt][3],
                     kBase + (uint32_t)((nrow * FSTR + col) * 4));
            }
#pragma unroll
            for (int nf = 0; nf < 8; ++nf) {
                int bt = nf >> 1, hi = (nf & 1) * 2;
                mma_tf32(sacc[nf][0], sacc[nf][1], sacc[nf][2], sacc[nf][3],
                         qf[kk8][0], qf[kk8][1], qf[kk8][2], qf[kk8][3],
                         bfr[bt][hi], bfr[bt][hi + 1]);
            }
        }

        // ---- online softmax ----
#pragma unroll
        for (int hh = 0; hh < 2; ++hh) {
            int row = q0 + warp * 16 + gid + hh * 8;
            float mloc = -1e30f;
#pragma unroll
            for (int nf = 0; nf < 8; ++nf) {
                float s0 = sacc[nf][hh * 2]     * SCALE_;
                float s1 = sacc[nf][hh * 2 + 1] * SCALE_;
                if (t == qt) {
                    int col = k0 + nf * 8 + tig * 2;
                    if (col     > row) s0 = -1e30f;
                    if (col + 1 > row) s1 = -1e30f;
                }
                sacc[nf][hh * 2] = s0; sacc[nf][hh * 2 + 1] = s1;
                mloc = fmaxf(mloc, fmaxf(s0, s1));
            }
            mloc = fmaxf(mloc, __shfl_xor_sync(0xffffffffu, mloc, 1));
            mloc = fmaxf(mloc, __shfl_xor_sync(0xffffffffu, mloc, 2));
            float mnew  = fmaxf(mrow[hh], mloc);
            float alpha = __expf(mrow[hh] - mnew);
            mrow[hh] = mnew;
            float rs = 0.f;
#pragma unroll
            for (int nf = 0; nf < 8; ++nf) {
                float p0 = __expf(sacc[nf][hh * 2]     - mnew);
                float p1 = __expf(sacc[nf][hh * 2 + 1] - mnew);
                sacc[nf][hh * 2] = p0; sacc[nf][hh * 2 + 1] = p1;
                rs += p0 + p1;
            }
            rs += __shfl_xor_sync(0xffffffffu, rs, 1);
            rs += __shfl_xor_sync(0xffffffffu, rs, 2);
            lrow[hh] = lrow[hh] * alpha + rs;
#pragma unroll
            for (int nf = 0; nf < 8; ++nf) {
                oacc[nf][hh * 2]     *= alpha;
                oacc[nf][hh * 2 + 1] *= alpha;
            }
            int prow = warp * 16 + gid + hh * 8;   // warp-private rows
#pragma unroll
            for (int nf = 0; nf < 8; ++nf) {
                *(float2*)&PQ[prow * FSTR + nf * 8 + tig * 2] =
                    make_float2(f2tff(sacc[nf][hh * 2]), f2tff(sacc[nf][hh * 2 + 1]));
            }
        }
        __syncwarp();

        // ---- O += P V ----  (B-frags straight from natural-layout Vs)
#pragma unroll
        for (int kk8 = 0; kk8 < 8; ++kk8) {
            uint32_t pf[4];
            {
                int row = warp * 16 + (lane & 15);
                int col = kk8 * 8 + (lane >> 4) * 4;
                ldm4(pf[0], pf[1], pf[2], pf[3],
                     sPQ + (uint32_t)((row * FSTR + col) * 4));
            }
            const float* v0r = &Vs[(vRow0 + kk8 * 8 + tig)     * FSTRV + gid];
            const float* v1r = &Vs[(vRow0 + kk8 * 8 + tig + 4) * FSTRV + gid];
#pragma unroll
            for (int nf = 0; nf < 8; ++nf) {
                uint32_t b0 = __float_as_uint(v0r[nf * 8]);
                uint32_t b1 = __float_as_uint(v1r[nf * 8]);
                mma_tf32(oacc[nf][0], oacc[nf][1], oacc[nf][2], oacc[nf][3],
                         pf[0], pf[1], pf[2], pf[3], b0, b1);
            }
        }
        __syncthreads();   // all reads of this buf done before it is refilled
    }

    // ---- epilogue (tf32-rounded for the O-proj GEMM) ----
#pragma unroll
    for (int hh = 0; hh < 2; ++hh) {
        int row = q0 + warp * 16 + gid + hh * 8;
        float inv = 1.f / lrow[hh];
#pragma unroll
        for (int nf = 0; nf < 8; ++nf) {
            *(float2*)(O + (size_t)(b * S_ + row) * (NH_ * D_) + h * D_ + nf * 8 + tig * 2) =
                make_float2(f2tff(oacc[nf][hh * 2] * inv), f2tff(oacc[nf][hh * 2 + 1] * inv));
        }
    }
}

// ---------------- launch ------------------------------------------------------
extern "C" void kernel_launch(void* const* d_in, const int* in_sizes, int n_in,
                              void* d_out, int out_size)
{
    const float* x    = (const float*)d_in[0];
    const float* cosb = (const float*)d_in[1];
    const float* sinb = (const float*)d_in[2];
    // d_in[3] = causal mask (structure hard-coded)
    const float* wq   = (const float*)d_in[4];
    const float* wk   = (const float*)d_in[5];
    const float* wv   = (const float*)d_in[6];
    const float* wo   = (const float*)d_in[7];
    float* out = (float*)d_out;

    float *q, *k, *v, *o, *xc, *wqc, *wkc, *wvc, *woc;
    cudaGetSymbolAddress((void**)&q,   g_q);
    cudaGetSymbolAddress((void**)&k,   g_k);
    cudaGetSymbolAddress((void**)&v,   g_v);
    cudaGetSymbolAddress((void**)&o,   g_o);
    cudaGetSymbolAddress((void**)&xc,  g_xc);
    cudaGetSymbolAddress((void**)&wqc, g_wqc);
    cudaGetSymbolAddress((void**)&wkc, g_wkc);
    cudaGetSymbolAddress((void**)&wvc, g_wvc);
    cudaGetSymbolAddress((void**)&woc, g_woc);

    cudaFuncSetAttribute(gemm_tf32,  cudaFuncAttributeMaxDynamicSharedMemorySize, GEMM_SMEM);
    cudaFuncSetAttribute(flash_tf32, cudaFuncAttributeMaxDynamicSharedMemorySize, FLASH_SMEM);

    const int M = B_ * S_;  // 4096

    // pre-round inputs/weights to tf32
    auto cvt = [&](float* dst, const float* src, size_t n) {
        int n4 = (int)(n / 4);
        cvt_kernel<<<(n4 + 255) / 256, 256>>>(dst, src, n4);
    };
    cvt(xc,  x,  (size_t)M * H_);
    cvt(wqc, wq, (size_t)NH_  * D_ * H_);
    cvt(wkc, wk, (size_t)NKV_ * D_ * H_);
    cvt(wvc, wv, (size_t)NKV_ * D_ * H_);
    cvt(woc, wo, (size_t)H_ * NH_ * D_);

    dim3 gq(NH_  * D_ / 128, M / 128);   // (16,32)
    dim3 gk(NKV_ * D_ / 128, M / 128);   // (4,32)
    gemm_tf32<<<gq, 256, GEMM_SMEM>>>(xc, wqc, q, M, NH_  * D_, H_, 0);
    gemm_tf32<<<gk, 256, GEMM_SMEM>>>(xc, wkc, k, M, NKV_ * D_, H_, 0);
    gemm_tf32<<<gk, 256, GEMM_SMEM>>>(xc, wvc, v, M, NKV_ * D_, H_, 1);  // round: flash reads raw

    int tq = B_ * S_ * NH_  * (D_ / 2);
    int tk = B_ * S_ * NKV_ * (D_ / 2);
    rope_kernel<<<(tq + 255) / 256, 256>>>(q, cosb, sinb, NH_);   // writes rounded
    rope_kernel<<<(tk + 255) / 256, 256>>>(k, cosb, sinb, NKV_);  // writes rounded

    dim3 gf(S_ / 64, B_ * NH_);          // (32, 64)
    flash_tf32<<<gf, 128, FLASH_SMEM>>>(q, k, v, o);              // writes rounded o

    gemm_tf32<<<gq, 256, GEMM_SMEM>>>(o, woc, out, M, H_, NH_ * D_, 0);
}

// round 6
// speedup vs baseline: 3.7171x; 1.0015x over previous
#include <cuda_runtime.h>
#include <cstdint>
#include <math.h>

#define B_    2
#define S_    2048
#define H_    2048
#define NH_   32
#define NKV_  8
#define D_    64
#define SCALE_ 0.125f   // D^-0.5

#define KVW   1024      // fused K|V row width

// ---------------- scratch (device globals; no allocs allowed) ----------------
__device__ float g_q [(size_t)B_*S_*NH_*D_];          // 33.5 MB
__device__ float g_kv[(size_t)B_*S_*KVW];             // 16.8 MB  cols 0-511=K, 512-1023=V
__device__ float g_o [(size_t)B_*S_*NH_*D_];          // 33.5 MB
__device__ float g_xc [(size_t)B_*S_*H_];             // tf32-rounded x
__device__ float g_wqc [(size_t)NH_*D_*H_];
__device__ float g_wkvc[(size_t)2*NKV_*D_*H_];        // [wk ; wv]
__device__ float g_woc [(size_t)H_*NH_*D_];

// ---------------- helpers -----------------------------------------------------
__device__ __forceinline__ uint32_t f2tf(float f) {
    uint32_t u;
    asm("cvt.rna.tf32.f32 %0, %1;" : "=r"(u) : "f"(f));
    return u;
}
__device__ __forceinline__ float f2tff(float f) { return __uint_as_float(f2tf(f)); }

__device__ __forceinline__ void cp16(uint32_t smem, const void* gmem) {
    asm volatile("cp.async.cg.shared.global [%0], [%1], 16;" :: "r"(smem), "l"(gmem));
}
__device__ __forceinline__ void cp_commit() {
    asm volatile("cp.async.commit_group;" ::: "memory");
}

__device__ __forceinline__ void ldm4(uint32_t& r0, uint32_t& r1, uint32_t& r2, uint32_t& r3,
                                     uint32_t addr) {
    asm volatile("ldmatrix.sync.aligned.m8n8.x4.shared.b16 {%0,%1,%2,%3}, [%4];"
                 : "=r"(r0), "=r"(r1), "=r"(r2), "=r"(r3) : "r"(addr));
}

__device__ __forceinline__ void mma_tf32(float& c0, float& c1, float& c2, float& c3,
                                         uint32_t a0, uint32_t a1, uint32_t a2, uint32_t a3,
                                         uint32_t b0, uint32_t b1) {
    asm volatile(
        "mma.sync.aligned.m16n8k8.row.col.f32.tf32.tf32.f32 "
        "{%0,%1,%2,%3},{%4,%5,%6,%7},{%8,%9},{%0,%1,%2,%3};"
        : "+f"(c0), "+f"(c1), "+f"(c2), "+f"(c3)
        : "r"(a0), "r"(a1), "r"(a2), "r"(a3), "r"(b0), "r"(b1));
}

// ---------------- tf32 pre-round kernel ---------------------------------------
__global__ void cvt_kernel(float* __restrict__ dst, const float* __restrict__ src, int n4) {
    int i = blockIdx.x * blockDim.x + threadIdx.x;
    if (i >= n4) return;
    float4 v = ((const float4*)src)[i];
    ((float4*)dst)[i] = make_float4(f2tff(v.x), f2tff(v.y), f2tff(v.z), f2tff(v.w));
}

// ---------------- tf32 GEMM: C[M,N] = A[M,K] * W[N,K]^T -----------------------
// Inputs pre-rounded. 128x128x32 tiles, 3-stage cp.async pipeline.
// Columns >= round_n0 get tf32-rounded on output (V half of the fused KV GEMM).
#define ASTR 36
#define STAGES 3
#define GEMM_SMEM (STAGES * 2 * 128 * ASTR * 4)   // 110592 B

__global__ void __launch_bounds__(256) gemm_tf32(
    const float* __restrict__ A, const float* __restrict__ W,
    float* __restrict__ C, int M, int N, int K, int round_n0)
{
    extern __shared__ float sm[];
    float* As = sm;
    float* Bs = sm + STAGES * 128 * ASTR;

    const int tid  = threadIdx.x;
    const int warp = tid >> 5, lane = tid & 31;
    const int gid  = lane >> 2, tig = lane & 3;
    const int wm   = warp >> 2, wn = warp & 3;
    const int bm   = blockIdx.y * 128, bn = blockIdx.x * 128;

    const int srow = tid >> 3;
    const int sc4  = (tid & 7) * 4;

    const float* Ag = A + (size_t)bm * K;
    const float* Wg = W + (size_t)bn * K;

    const uint32_t sA = (uint32_t)__cvta_generic_to_shared(As);
    const uint32_t sB = (uint32_t)__cvta_generic_to_shared(Bs);

    float acc[4][4][4];
#pragma unroll
    for (int mt = 0; mt < 4; ++mt)
#pragma unroll
        for (int nf = 0; nf < 4; ++nf)
#pragma unroll
            for (int r = 0; r < 4; ++r) acc[mt][nf][r] = 0.f;

    auto issue = [&](int st, int k0) {
        uint32_t baseA = sA + (uint32_t)(st * 128 * ASTR * 4);
        uint32_t baseB = sB + (uint32_t)(st * 128 * ASTR * 4);
#pragma unroll
        for (int i = 0; i < 4; ++i) {
            int row = srow + 32 * i;
            cp16(baseA + (uint32_t)((row * ASTR + sc4) * 4),
                 Ag + (size_t)row * K + k0 + sc4);
            cp16(baseB + (uint32_t)((row * ASTR + sc4) * 4),
                 Wg + (size_t)row * K + k0 + sc4);
        }
        cp_commit();
    };

    const int nk = K / 32;
    issue(0, 0);
    issue(1, 32);

    for (int it = 0; it < nk; ++it) {
        if (it + 1 < nk) { asm volatile("cp.async.wait_group 1;" ::: "memory"); }
        else             { asm volatile("cp.async.wait_group 0;" ::: "memory"); }
        __syncthreads();

        if (it + 2 < nk) issue((it + 2) % STAGES, (it + 2) * 32);

        const int st  = it % STAGES;
        const uint32_t aBase = sA + (uint32_t)(st * 128 * ASTR * 4);
        const uint32_t bBase = sB + (uint32_t)(st * 128 * ASTR * 4);

#pragma unroll
        for (int kk = 0; kk < 32; kk += 8) {
            uint32_t af[4][4];
#pragma unroll
            for (int mt = 0; mt < 4; ++mt) {
                int row = wm * 64 + mt * 16 + (lane & 15);
                int col = kk + (lane >> 4) * 4;
                ldm4(af[mt][0], af[mt][1], af[mt][2], af[mt][3],
                     aBase + (uint32_t)((row * ASTR + col) * 4));
            }
            uint32_t bf[2][4];
#pragma unroll
            for (int bt = 0; bt < 2; ++bt) {
                int nrow = wn * 32 + bt * 16 + ((lane >> 4) << 3) + (lane & 7);
                int col  = kk + ((lane >> 3) & 1) * 4;
                ldm4(bf[bt][0], bf[bt][1], bf[bt][2], bf[bt][3],
                     bBase + (uint32_t)((nrow * ASTR + col) * 4));
            }
#pragma unroll
            for (int mt = 0; mt < 4; ++mt)
#pragma unroll
                for (int nf = 0; nf < 4; ++nf) {
                    int bt = nf >> 1, hi = (nf & 1) * 2;
                    mma_tf32(acc[mt][nf][0], acc[mt][nf][1], acc[mt][nf][2], acc[mt][nf][3],
                             af[mt][0], af[mt][1], af[mt][2], af[mt][3],
                             bf[bt][hi], bf[bt][hi + 1]);
                }
        }
    }

    const bool rnd = (bn >= round_n0);
#pragma unroll
    for (int mt = 0; mt < 4; ++mt)
#pragma unroll
        for (int nf = 0; nf < 4; ++nf) {
            int row = bm + wm * 64 + mt * 16 + gid;
            int col = bn + wn * 32 + nf * 8 + tig * 2;
            float v0 = acc[mt][nf][0], v1 = acc[mt][nf][1];
            float v2 = acc[mt][nf][2], v3 = acc[mt][nf][3];
            if (rnd) { v0 = f2tff(v0); v1 = f2tff(v1); v2 = f2tff(v2); v3 = f2tff(v3); }
            *(float2*)(C + (size_t)row * N + col)       = make_float2(v0, v1);
            *(float2*)(C + (size_t)(row + 8) * N + col) = make_float2(v2, v3);
        }
}

// ---------------- RoPE (in-place, writes tf32-rounded; strided) ---------------
__global__ void rope_kernel(float* __restrict__ buf,
                            const float* __restrict__ cosb,
                            const float* __restrict__ sinb,
                            int nheads, int rowstride)
{
    int idx = blockIdx.x * blockDim.x + threadIdx.x;
    int total = B_ * S_ * nheads * (D_ / 2);
    if (idx >= total) return;
    int d   = idx % (D_ / 2);
    int h   = (idx / (D_ / 2)) % nheads;
    int row = idx / ((D_ / 2) * nheads);
    size_t base = (size_t)row * rowstride + (size_t)h * D_;
    float q1 = buf[base + d];
    float q2 = buf[base + d + D_ / 2];
    float c1 = cosb[(size_t)row * D_ + d];
    float c2 = cosb[(size_t)row * D_ + d + D_ / 2];
    float s1 = sinb[(size_t)row * D_ + d];
    float s2 = sinb[(size_t)row * D_ + d + D_ / 2];
    buf[base + d]          = f2tff(q1 * c1 - q2 * s1);
    buf[base + d + D_ / 2] = f2tff(q2 * c2 + q1 * s2);
}

// ---------------- tf32 flash attention (causal, GQA, 2 heads/block) -----------
// Block: 2 q-heads x 64 q-rows, 256 threads (8 warps: warp>>2 = head,
// warp&3 = m16 strip). K/V shared by both heads -> global KV traffic halved.
#define FSTR  68
#define FSTRV 72
#define FLASH_SMEM ((128 * FSTR + 2 * 64 * FSTR + 2 * 64 * FSTRV) * 4)   // 106496 B

__global__ void __launch_bounds__(256, 1) flash_tf32(
    const float* __restrict__ Q, const float* __restrict__ KV,
    float* __restrict__ O)
{
    extern __shared__ float sm[];
    float* PQ = sm;                          // [128][FSTR]  Q tiles then P tiles
    float* Ks = sm + 128 * FSTR;             // [2][64][FSTR]
    float* Vs = sm + 128 * FSTR + 2 * 64 * FSTR;  // [2][64][FSTRV]

    const int tid  = threadIdx.x;
    const int warp = tid >> 5, lane = tid & 31;
    const int wp   = warp & 3, hp = warp >> 2;     // strip, head-in-pair
    const int gid  = lane >> 2, tig = lane & 3;

    const int qt = (gridDim.x - 1) - blockIdx.x;   // big blocks first
    const int q0 = qt * 64;
    const int by = blockIdx.y;                      // 0..31
    const int b    = by >> 4;
    const int kvh  = (by & 15) >> 1;
    const int pair = by & 1;
    const int hA   = kvh * 4 + pair * 2;            // this block: heads hA, hA+1
    const int h    = hA + hp;                       // this warp's head

    const float* Kb = KV + (size_t)b * S_ * KVW + (size_t)kvh * D_;
    const float* Vb = Kb + 512;

    const uint32_t sPQ = (uint32_t)__cvta_generic_to_shared(PQ);
    const uint32_t sKs = (uint32_t)__cvta_generic_to_shared(Ks);
    const uint32_t sVs = (uint32_t)__cvta_generic_to_shared(Vs);

    const int cr16 = tid >> 4;            // 0..15
    const int cc4  = (tid & 15) * 4;      // 0..60

    auto issue_kv = [&](int t, int buf) {
        const int k0 = t * 64;
#pragma unroll
        for (int i = 0; i < 4; ++i) {
            int r = cr16 + 16 * i;
            cp16(sKs + (uint32_t)(((buf * 64 + r) * FSTR  + cc4) * 4),
                 Kb + (size_t)(k0 + r) * KVW + cc4);
            cp16(sVs + (uint32_t)(((buf * 64 + r) * FSTRV + cc4) * 4),
                 Vb + (size_t)(k0 + r) * KVW + cc4);
        }
        cp_commit();
    };

    // stage both heads' Q tiles (group 0), then KV tile 0 (group 1)
#pragma unroll
    for (int i = 0; i < 8; ++i) {
        int idx = tid + i * 256;
        int r = idx >> 4, c4 = (idx & 15) * 4;     // r: 0..127
        int hd  = r >> 6;                           // 0/1
        int row = q0 + (r & 63);
        cp16(sPQ + (uint32_t)((r * FSTR + c4) * 4),
             Q + (size_t)(b * S_ + row) * (NH_ * D_) + (hA + hd) * D_ + c4);
    }
    cp_commit();
    issue_kv(0, 0);

    asm volatile("cp.async.wait_group 1;" ::: "memory");   // Q ready
    __syncthreads();

    uint32_t qf[8][4];
#pragma unroll
    for (int kk8 = 0; kk8 < 8; ++kk8) {
        int row = hp * 64 + wp * 16 + (lane & 15);
        int col = kk8 * 8 + (lane >> 4) * 4;
        ldm4(qf[kk8][0], qf[kk8][1], qf[kk8][2], qf[kk8][3],
             sPQ + (uint32_t)((row * FSTR + col) * 4));
    }

    float oacc[8][4];
#pragma unroll
    for (int nf = 0; nf < 8; ++nf)
#pragma unroll
        for (int r = 0; r < 4; ++r) oacc[nf][r] = 0.f;
    float mrow[2] = {-1e30f, -1e30f}, lrow[2] = {0.f, 0.f};

    for (int t = 0; t <= qt; ++t) {
        const int k0  = t * 64;
        const int buf = t & 1;

        asm volatile("cp.async.wait_group 0;" ::: "memory");
        __syncthreads();
        if (t < qt) issue_kv(t + 1, buf ^ 1);

        const uint32_t kBase = sKs + (uint32_t)(buf * 64 * FSTR * 4);
        const int      vRow0 = buf * 64;

        // ---- S = Q K^T ----
        float sacc[8][4];
#pragma unroll
        for (int nf = 0; nf < 8; ++nf)
#pragma unroll
            for (int r = 0; r < 4; ++r) sacc[nf][r] = 0.f;

#pragma unroll
        for (int kk8 = 0; kk8 < 8; ++kk8) {
            uint32_t bfr[4][4];
#pragma unroll
            for (int bt = 0; bt < 4; ++bt) {
                int nrow = bt * 16 + ((lane >> 4) << 3) + (lane & 7);
                int col  = kk8 * 8 + ((lane >> 3) & 1) * 4;
                ldm4(bfr[bt][0], bfr[bt][1], bfr[bt][2], bfr[bt][3],
                     kBase + (uint32_t)((nrow * FSTR + col) * 4));
            }
#pragma unroll
            for (int nf = 0; nf < 8; ++nf) {
                int bt = nf >> 1, hi = (nf & 1) * 2;
                mma_tf32(sacc[nf][0], sacc[nf][1], sacc[nf][2], sacc[nf][3],
                         qf[kk8][0], qf[kk8][1], qf[kk8][2], qf[kk8][3],
                         bfr[bt][hi], bfr[bt][hi + 1]);
            }
        }

        // ---- online softmax ----
#pragma unroll
        for (int hh = 0; hh < 2; ++hh) {
            int row = q0 + wp * 16 + gid + hh * 8;
            float mloc = -1e30f;
#pragma unroll
            for (int nf = 0; nf < 8; ++nf) {
                float s0 = sacc[nf][hh * 2]     * SCALE_;
                float s1 = sacc[nf][hh * 2 + 1] * SCALE_;
                if (t == qt) {
                    int col = k0 + nf * 8 + tig * 2;
                    if (col     > row) s0 = -1e30f;
                    if (col + 1 > row) s1 = -1e30f;
                }
                sacc[nf][hh * 2] = s0; sacc[nf][hh * 2 + 1] = s1;
                mloc = fmaxf(mloc, fmaxf(s0, s1));
            }
            mloc = fmaxf(mloc, __shfl_xor_sync(0xffffffffu, mloc, 1));
            mloc = fmaxf(mloc, __shfl_xor_sync(0xffffffffu, mloc, 2));
            float mnew  = fmaxf(mrow[hh], mloc);
            float alpha = __expf(mrow[hh] - mnew);
            mrow[hh] = mnew;
            float rs = 0.f;
#pragma unroll
            for (int nf = 0; nf < 8; ++nf) {
                float p0 = __expf(sacc[nf][hh * 2]     - mnew);
                float p1 = __expf(sacc[nf][hh * 2 + 1] - mnew);
                sacc[nf][hh * 2] = p0; sacc[nf][hh * 2 + 1] = p1;
                rs += p0 + p1;
            }
            rs += __shfl_xor_sync(0xffffffffu, rs, 1);
            rs += __shfl_xor_sync(0xffffffffu, rs, 2);
            lrow[hh] = lrow[hh] * alpha + rs;
#pragma unroll
            for (int nf = 0; nf < 8; ++nf) {
                oacc[nf][hh * 2]     *= alpha;
                oacc[nf][hh * 2 + 1] *= alpha;
            }
            int prow = hp * 64 + wp * 16 + gid + hh * 8;   // warp-private rows
#pragma unroll
            for (int nf = 0; nf < 8; ++nf) {
                *(float2*)&PQ[prow * FSTR + nf * 8 + tig * 2] =
                    make_float2(f2tff(sacc[nf][hh * 2]), f2tff(sacc[nf][hh * 2 + 1]));
            }
        }
        __syncwarp();

        // ---- O += P V ----  (B-frags straight from natural-layout Vs)
#pragma unroll
        for (int kk8 = 0; kk8 < 8; ++kk8) {
            uint32_t pf[4];
            {
                int row = hp * 64 + wp * 16 + (lane & 15);
                int col = kk8 * 8 + (lane >> 4) * 4;
                ldm4(pf[0], pf[1], pf[2], pf[3],
                     sPQ + (uint32_t)((row * FSTR + col) * 4));
            }
            const float* v0r = &Vs[(vRow0 + kk8 * 8 + tig)     * FSTRV + gid];
            const float* v1r = &Vs[(vRow0 + kk8 * 8 + tig + 4) * FSTRV + gid];
#pragma unroll
            for (int nf = 0; nf < 8; ++nf) {
                uint32_t b0 = __float_as_uint(v0r[nf * 8]);
                uint32_t b1 = __float_as_uint(v1r[nf * 8]);
                mma_tf32(oacc[nf][0], oacc[nf][1], oacc[nf][2], oacc[nf][3],
                         pf[0], pf[1], pf[2], pf[3], b0, b1);
            }
        }
        __syncthreads();   // all warps done with this buf before refill
    }

    // ---- epilogue (tf32-rounded for the O-proj GEMM) ----
#pragma unroll
    for (int hh = 0; hh < 2; ++hh) {
        int row = q0 + wp * 16 + gid + hh * 8;
        float inv = 1.f / lrow[hh];
#pragma unroll
        for (int nf = 0; nf < 8; ++nf) {
            *(float2*)(O + (size_t)(b * S_ + row) * (NH_ * D_) + h * D_ + nf * 8 + tig * 2) =
                make_float2(f2tff(oacc[nf][hh * 2] * inv), f2tff(oacc[nf][hh * 2 + 1] * inv));
        }
    }
}

// ---------------- launch ------------------------------------------------------
extern "C" void kernel_launch(void* const* d_in, const int* in_sizes, int n_in,
                              void* d_out, int out_size)
{
    const float* x    = (const float*)d_in[0];
    const float* cosb = (const float*)d_in[1];
    const float* sinb = (const float*)d_in[2];
    // d_in[3] = causal mask (structure hard-coded)
    const float* wq   = (const float*)d_in[4];
    const float* wk   = (const float*)d_in[5];
    const float* wv   = (const float*)d_in[6];
    const float* wo   = (const float*)d_in[7];
    float* out = (float*)d_out;

    float *q, *kv, *o, *xc, *wqc, *wkvc, *woc;
    cudaGetSymbolAddress((void**)&q,    g_q);
    cudaGetSymbolAddress((void**)&kv,   g_kv);
    cudaGetSymbolAddress((void**)&o,    g_o);
    cudaGetSymbolAddress((void**)&xc,   g_xc);
    cudaGetSymbolAddress((void**)&wqc,  g_wqc);
    cudaGetSymbolAddress((void**)&wkvc, g_wkvc);
    cudaGetSymbolAddress((void**)&woc,  g_woc);

    cudaFuncSetAttribute(gemm_tf32,  cudaFuncAttributeMaxDynamicSharedMemorySize, GEMM_SMEM);
    cudaFuncSetAttribute(flash_tf32, cudaFuncAttributeMaxDynamicSharedMemorySize, FLASH_SMEM);

    const int M = B_ * S_;  // 4096
    const int NOROUND = 1 << 30;

    auto cvt = [&](float* dst, const float* src, size_t n) {
        int n4 = (int)(n / 4);
        cvt_kernel<<<(n4 + 255) / 256, 256>>>(dst, src, n4);
    };
    cvt(xc,   x,  (size_t)M * H_);
    cvt(wqc,  wq, (size_t)NH_ * D_ * H_);
    cvt(wkvc,                      wk, (size_t)NKV_ * D_ * H_);
    cvt(wkvc + (size_t)NKV_*D_*H_, wv, (size_t)NKV_ * D_ * H_);
    cvt(woc,  wo, (size_t)H_ * NH_ * D_);

    dim3 gq (NH_ * D_ / 128, M / 128);   // (16,32)
    dim3 gkv(KVW      / 128, M / 128);   // (8,32) fused K|V
    gemm_tf32<<<gq,  256, GEMM_SMEM>>>(xc, wqc,  q,  M, NH_ * D_, H_, NOROUND);
    gemm_tf32<<<gkv, 256, GEMM_SMEM>>>(xc, wkvc, kv, M, KVW,      H_, 512);   // round V half

    int tq = B_ * S_ * NH_  * (D_ / 2);
    int tk = B_ * S_ * NKV_ * (D_ / 2);
    rope_kernel<<<(tq + 255) / 256, 256>>>(q,  cosb, sinb, NH_,  NH_ * D_);
    rope_kernel<<<(tk + 255) / 256, 256>>>(kv, cosb, sinb, NKV_, KVW);

    dim3 gf(S_ / 64, 32);                // (32, b*kvh*pair = 32)
    flash_tf32<<<gf, 256, FLASH_SMEM>>>(q, kv, o);

    gemm_tf32<<<gq, 256, GEMM_SMEM>>>(o, woc, out, M, H_, NH_ * D_, NOROUND);
}